// round 5
// baseline (speedup 1.0000x reference)
#include <cuda_runtime.h>
#include <cuda_bf16.h>
#include <cstdint>
#include <math.h>

#define BATCH 8
#define LSEQ  2048
#define DDIM  512

// ---------------------------------------------------------------------------
// Device-global scratch (module-load allocation; no runtime allocs).
// ---------------------------------------------------------------------------
static __device__ float g_P[(size_t)BATCH * LSEQ * LSEQ];                           // 128 MiB logits
static __device__ __align__(128) __nv_bfloat16 g_qh[(size_t)BATCH * LSEQ * DDIM];
static __device__ __align__(128) __nv_bfloat16 g_ql[(size_t)BATCH * LSEQ * DDIM];
static __device__ __align__(128) __nv_bfloat16 g_kh[(size_t)BATCH * LSEQ * DDIM];
static __device__ __align__(128) __nv_bfloat16 g_kl[(size_t)BATCH * LSEQ * DDIM];
static __device__ __align__(128) __nv_bfloat16 g_vth[(size_t)BATCH * DDIM * LSEQ];  // v transposed [b][d][j]
static __device__ __align__(128) __nv_bfloat16 g_vtl[(size_t)BATCH * DDIM * LSEQ];
static __device__ __align__(128) __nv_bfloat16 g_ah[(size_t)BATCH * LSEQ * LSEQ];   // attn hi/lo
static __device__ __align__(128) __nv_bfloat16 g_al[(size_t)BATCH * LSEQ * LSEQ];

// ---------------------------------------------------------------------------
// PTX helpers (sm_80+ only; base sm_103 target has no tcgen05)
// ---------------------------------------------------------------------------
__device__ __forceinline__ uint32_t smem_u32(const void* p) {
    uint32_t a;
    asm("{ .reg .u64 t; cvta.to.shared.u64 t, %1; cvt.u32.u64 %0, t; }" : "=r"(a) : "l"(p));
    return a;
}
__device__ __forceinline__ void ldsm4(uint32_t* r, uint32_t addr) {
    asm volatile("ldmatrix.sync.aligned.m8n8.x4.shared.b16 {%0,%1,%2,%3}, [%4];"
                 : "=r"(r[0]), "=r"(r[1]), "=r"(r[2]), "=r"(r[3]) : "r"(addr));
}
#define MMA16816(d, a, b0, b1)                                                     \
    asm volatile("mma.sync.aligned.m16n8k16.row.col.f32.bf16.bf16.f32 "            \
                 "{%0,%1,%2,%3},{%4,%5,%6,%7},{%8,%9},{%0,%1,%2,%3};"              \
                 : "+f"((d)[0]), "+f"((d)[1]), "+f"((d)[2]), "+f"((d)[3])          \
                 : "r"((a)[0]), "r"((a)[1]), "r"((a)[2]), "r"((a)[3]),             \
                   "r"(b0), "r"(b1))
#define CP_ASYNC16(dst, src) \
    asm volatile("cp.async.cg.shared.global [%0], [%1], 16;" :: "r"(dst), "l"(src))
#define CP_COMMIT()  asm volatile("cp.async.commit_group;" ::: "memory")
#define CP_WAITN(n)  asm volatile("cp.async.wait_group %0;" :: "n"(n) : "memory")

__device__ __forceinline__ void split2(float v, __nv_bfloat16& h, __nv_bfloat16& l) {
    h = __float2bfloat16(v);
    l = __float2bfloat16(v - __bfloat162float(h));
}

// Swizzled byte offset within a 128-row x 64-byte tile.
// seg (16B unit, 0..3) is XORed with bits (row>>1)&3 -> conflict-free ldmatrix.
__device__ __forceinline__ uint32_t swz(int row, int seg) {
    return (uint32_t)(row * 64 + ((seg ^ ((row >> 1) & 3)) << 4));
}

// ---------------------------------------------------------------------------
// Kernel 1: split projections. q,k stored [b][i][d] hi/lo; v stored transposed
// [b][d][j] hi/lo via smem tile transpose. Block handles 64(j) x 64(d).
// ---------------------------------------------------------------------------
__global__ __launch_bounds__(256) void split_kernel(const float* __restrict__ x,
                                                    const float* __restrict__ qw,
                                                    const float* __restrict__ kw,
                                                    const float* __restrict__ vw)
{
    __shared__ __nv_bfloat16 vh_s[64][66];
    __shared__ __nv_bfloat16 vl_s[64][66];

    const int b  = blockIdx.z;
    const int j0 = blockIdx.x * 64;
    const int d0 = blockIdx.y * 64;
    const int t  = threadIdx.x;

    union U4 { __nv_bfloat16 h[4]; uint2 u; };

#pragma unroll
    for (int it = 0; it < 4; ++it) {
        const int id = t + it * 256;
        const int r  = id >> 4;
        const int c  = (id & 15) * 4;
        const size_t gx = ((size_t)b * LSEQ + j0 + r) * DDIM + d0 + c;
        const size_t gw = (size_t)(j0 + r) * DDIM + d0 + c;
        const float4 xv = *(const float4*)(x  + gx);
        const float4 q4 = *(const float4*)(qw + gw);
        const float4 k4 = *(const float4*)(kw + gw);
        const float4 v4 = *(const float4*)(vw + gw);

        U4 qh, ql, kh, kl;
        split2(xv.x * q4.x, qh.h[0], ql.h[0]); split2(xv.y * q4.y, qh.h[1], ql.h[1]);
        split2(xv.z * q4.z, qh.h[2], ql.h[2]); split2(xv.w * q4.w, qh.h[3], ql.h[3]);
        split2(xv.x * k4.x, kh.h[0], kl.h[0]); split2(xv.y * k4.y, kh.h[1], kl.h[1]);
        split2(xv.z * k4.z, kh.h[2], kl.h[2]); split2(xv.w * k4.w, kh.h[3], kl.h[3]);
        *(uint2*)(g_qh + gx) = qh.u;  *(uint2*)(g_ql + gx) = ql.u;
        *(uint2*)(g_kh + gx) = kh.u;  *(uint2*)(g_kl + gx) = kl.u;

        __nv_bfloat16 vh0, vl0;
        split2(xv.x * v4.x, vh0, vl0); vh_s[r][c + 0] = vh0; vl_s[r][c + 0] = vl0;
        split2(xv.y * v4.y, vh0, vl0); vh_s[r][c + 1] = vh0; vl_s[r][c + 1] = vl0;
        split2(xv.z * v4.z, vh0, vl0); vh_s[r][c + 2] = vh0; vl_s[r][c + 2] = vl0;
        split2(xv.w * v4.w, vh0, vl0); vh_s[r][c + 3] = vh0; vl_s[r][c + 3] = vl0;
    }
    __syncthreads();

#pragma unroll
    for (int it = 0; it < 16; ++it) {
        const int id = t + it * 256;
        const int dr = id >> 6;
        const int jc = id & 63;
        const size_t go = ((size_t)b * DDIM + d0 + dr) * LSEQ + j0 + jc;
        g_vth[go] = vh_s[jc][dr];
        g_vtl[go] = vl_s[jc][dr];
    }
}

// ---------------------------------------------------------------------------
// Kernel 2/4: 3-product bf16 HMMA GEMM. D[m,n] = sum_k A[m,k]*B[n,k], with
// A = Ah+Al, B = Bh+Bl (lo*lo dropped). Block tile 128x128, K-chunk 32,
// 3-stage cp.async pipeline, XOR-swizzled smem, 8 warps 2(m)x4(n),
// warp tile 64x32. LDSMs interleaved under MMA shadows; prefetch issued
// before the pipeline wait.
// MODE 0: QK (K=512) -> scaled logits into g_P.
// MODE 1: AV (K=2048, A = attention hi/lo, B = v transposed) -> Cout.
// ---------------------------------------------------------------------------
template <int MODE>
__global__ __launch_bounds__(256, 2) void gemm3_kernel(float* __restrict__ Cout)
{
    extern __shared__ __align__(128) char dsm[];

    constexpr int K       = (MODE == 0) ? DDIM : LSEQ;
    constexpr int NC      = K / 32;
    constexpr int LDC     = (MODE == 0) ? LSEQ : DDIM;
    constexpr int TILE_B  = 128 * 64;      // 8192 bytes (128 rows x 32 bf16)
    constexpr int STAGE_B = 4 * TILE_B;    // 32768 bytes per stage
    const float scale = (MODE == 0) ? 0.3535533905932738f : 1.0f;

    const __nv_bfloat16* Ah = (MODE == 0) ? g_qh : g_ah;
    const __nv_bfloat16* Al = (MODE == 0) ? g_ql : g_al;
    const __nv_bfloat16* Bh = (MODE == 0) ? g_kh : g_vth;
    const __nv_bfloat16* Bl = (MODE == 0) ? g_kl : g_vtl;

    const int b  = blockIdx.z;
    const int n0 = blockIdx.x * 128;
    const int m0 = blockIdx.y * 128;
    const int t    = threadIdx.x;
    const int lane = t & 31;
    const int wid  = t >> 5;
    const int wm   = wid & 1;   // 0..1 -> 64-row slab
    const int wn   = wid >> 1;  // 0..3 -> 32-col slab

    const size_t bA = (MODE == 0) ? (size_t)LSEQ * DDIM : (size_t)LSEQ * LSEQ;
    const size_t bB = (MODE == 0) ? (size_t)LSEQ * DDIM : (size_t)DDIM * LSEQ;
    const size_t bC = (MODE == 0) ? (size_t)LSEQ * LSEQ : (size_t)LSEQ * DDIM;

    const __nv_bfloat16* pAh = Ah + b * bA + (size_t)m0 * K;
    const __nv_bfloat16* pAl = Al + b * bA + (size_t)m0 * K;
    const __nv_bfloat16* pBh = Bh + b * bB + (size_t)n0 * K;
    const __nv_bfloat16* pBl = Bl + b * bB + (size_t)n0 * K;
    float* Cb = ((MODE == 0) ? g_P : Cout) + b * bC + (size_t)m0 * LDC + n0;

    const uint32_t sb = smem_u32(dsm);

    // Prefetch one 128x32 hi/lo A+B chunk into stage slot s via cp.async.
    auto prefetch = [&](int c, int s) {
        const int k0 = c * 32;
        const uint32_t st = sb + s * STAGE_B;
        const __nv_bfloat16* gs[4] = { pAh + k0, pAl + k0, pBh + k0, pBl + k0 };
#pragma unroll
        for (int tt = 0; tt < 4; ++tt) {
            const uint32_t tb = st + tt * TILE_B;
#pragma unroll
            for (int i = 0; i < 2; ++i) {
                const int li  = t + i * 256;        // 0..511
                const int row = li >> 2;
                const int seg = li & 3;
                const uint32_t dst = tb + swz(row, seg);
                const void* src = gs[tt] + (size_t)row * K + seg * 8;
                CP_ASYNC16(dst, src);
            }
        }
        CP_COMMIT();
    };

    float acc[4][4][4];
#pragma unroll
    for (int mf = 0; mf < 4; ++mf)
#pragma unroll
        for (int nf = 0; nf < 4; ++nf)
#pragma unroll
            for (int i = 0; i < 4; ++i) acc[mf][nf][i] = 0.0f;

    const int lr   = lane & 15;       // ldmatrix row within 16
    const int lseg = lane >> 4;       // 0/1: which 16B (8-col) half

    prefetch(0, 0);
    if (NC > 1) prefetch(1, 1);

    int s = 0;              // stage slot of chunk c
    for (int c = 0; c < NC; ++c) {
        __syncthreads();     // all warps done reading the slot c+2 will reuse
        if (c + 2 < NC) {
            int s2 = s + 2; if (s2 >= 3) s2 -= 3;
            prefetch(c + 2, s2);
            CP_WAITN(2);     // pending {c+1, c+2} -> chunk c resident
        } else if (c + 1 < NC) {
            CP_WAITN(1);     // pending {c+1} -> chunk c resident
        } else {
            CP_WAITN(0);
        }
        __syncthreads();     // chunk c visible to all warps before LDSM

        const uint32_t st  = sb + s * STAGE_B;
        const uint32_t sAh = st;
        const uint32_t sAl = st + TILE_B;
        const uint32_t sBh = st + 2 * TILE_B;
        const uint32_t sBl = st + 3 * TILE_B;

#pragma unroll
        for (int ks = 0; ks < 2; ++ks) {
            const int segk = ks * 2 + lseg;
            uint32_t offA[4], offB[2];
#pragma unroll
            for (int mf = 0; mf < 4; ++mf)
                offA[mf] = swz(wm * 64 + mf * 16 + lr, segk);
#pragma unroll
            for (int p = 0; p < 2; ++p)
                offB[p] = swz(wn * 32 + p * 16 + lr, segk);

            uint32_t ah[4][4], al[4][4], bh[2][4], bl[2][4];

            // leading loads: ah + bh only
#pragma unroll
            for (int mf = 0; mf < 4; ++mf) ldsm4(ah[mf], sAh + offA[mf]);
#pragma unroll
            for (int p = 0; p < 2; ++p)    ldsm4(bh[p], sBh + offB[p]);

            // pass1 first half (mf 0..1) hides al loads
#pragma unroll
            for (int mf = 0; mf < 2; ++mf)
#pragma unroll
                for (int nf = 0; nf < 4; ++nf) {
                    const int p = nf >> 1, s2 = nf & 1;
                    MMA16816(acc[mf][nf], ah[mf], bh[p][s2], bh[p][s2 + 2]);
                }
#pragma unroll
            for (int mf = 0; mf < 4; ++mf) ldsm4(al[mf], sAl + offA[mf]);

            // pass1 second half (mf 2..3) hides bl loads
#pragma unroll
            for (int mf = 2; mf < 4; ++mf)
#pragma unroll
                for (int nf = 0; nf < 4; ++nf) {
                    const int p = nf >> 1, s2 = nf & 1;
                    MMA16816(acc[mf][nf], ah[mf], bh[p][s2], bh[p][s2 + 2]);
                }
#pragma unroll
            for (int p = 0; p < 2; ++p)    ldsm4(bl[p], sBl + offB[p]);

            // pass3 (al ready before bl)
#pragma unroll
            for (int mf = 0; mf < 4; ++mf)
#pragma unroll
                for (int nf = 0; nf < 4; ++nf) {
                    const int p = nf >> 1, s2 = nf & 1;
                    MMA16816(acc[mf][nf], al[mf], bh[p][s2], bh[p][s2 + 2]);
                }
            // pass2 (bl had pass3's shadow to land)
#pragma unroll
            for (int mf = 0; mf < 4; ++mf)
#pragma unroll
                for (int nf = 0; nf < 4; ++nf) {
                    const int p = nf >> 1, s2 = nf & 1;
                    MMA16816(acc[mf][nf], ah[mf], bl[p][s2], bl[p][s2 + 2]);
                }
        }
        if (++s == 3) s = 0;
    }

    // Epilogue: direct float2 stores (d0,d1 -> row r, d2,d3 -> row r+8)
#pragma unroll
    for (int mf = 0; mf < 4; ++mf) {
#pragma unroll
        for (int nf = 0; nf < 4; ++nf) {
            const int r0 = wm * 64 + mf * 16 + (lane >> 2);
            const int cc = wn * 32 + nf * 8 + (lane & 3) * 2;
            float2 v0, v1;
            v0.x = acc[mf][nf][0] * scale; v0.y = acc[mf][nf][1] * scale;
            v1.x = acc[mf][nf][2] * scale; v1.y = acc[mf][nf][3] * scale;
            *(float2*)&Cb[(size_t)r0 * LDC + cc]       = v0;
            *(float2*)&Cb[(size_t)(r0 + 8) * LDC + cc] = v1;
        }
    }
}

// ---------------------------------------------------------------------------
// Kernel 3: row softmax over g_P, output written as bf16 hi/lo attention.
// ---------------------------------------------------------------------------
__global__ __launch_bounds__(256) void softmax_kernel()
{
    const size_t row = blockIdx.x;
    const float* p = g_P + row * LSEQ;
    const int t = threadIdx.x;

    __shared__ float red[256];

    float v[8];
    float mx = -1e30f;
#pragma unroll
    for (int i = 0; i < 8; ++i) {
        v[i] = p[t + i * 256];
        mx = fmaxf(mx, v[i]);
    }
    red[t] = mx;
    __syncthreads();
    for (int s = 128; s > 0; s >>= 1) {
        if (t < s) red[t] = fmaxf(red[t], red[t + s]);
        __syncthreads();
    }
    const float m = red[0];
    __syncthreads();

    float sum = 0.0f;
#pragma unroll
    for (int i = 0; i < 8; ++i) {
        v[i] = __expf(v[i] - m);
        sum += v[i];
    }
    red[t] = sum;
    __syncthreads();
    for (int s = 128; s > 0; s >>= 1) {
        if (t < s) red[t] += red[t + s];
        __syncthreads();
    }
    const float inv = 1.0f / red[0];
#pragma unroll
    for (int i = 0; i < 8; ++i) {
        const float a = v[i] * inv;
        __nv_bfloat16 h, l;
        split2(a, h, l);
        const size_t o = row * LSEQ + t + i * 256;
        g_ah[o] = h;
        g_al[o] = l;
    }
}

// ---------------------------------------------------------------------------
extern "C" void kernel_launch(void* const* d_in, const int* in_sizes, int n_in,
                              void* d_out, int out_size)
{
    const float* x  = (const float*)d_in[0];
    const float* qw = (const float*)d_in[1];
    const float* kw = (const float*)d_in[2];
    const float* vw = (const float*)d_in[3];
    float* out = (float*)d_out;

    constexpr int SMEM = 98304;   // 3 stages x 32 KB
    cudaFuncSetAttribute(gemm3_kernel<0>, cudaFuncAttributeMaxDynamicSharedMemorySize, SMEM);
    cudaFuncSetAttribute(gemm3_kernel<1>, cudaFuncAttributeMaxDynamicSharedMemorySize, SMEM);

    split_kernel<<<dim3(LSEQ / 64, DDIM / 64, BATCH), 256>>>(x, qw, kw, vw);

    gemm3_kernel<0><<<dim3(LSEQ / 128, LSEQ / 128, BATCH), 256, SMEM>>>(nullptr);

    softmax_kernel<<<BATCH * LSEQ, 256>>>();

    gemm3_kernel<1><<<dim3(DDIM / 128, LSEQ / 128, BATCH), 256, SMEM>>>(out);
}

// round 6
// speedup vs baseline: 1.5087x; 1.5087x over previous
#include <cuda_runtime.h>
#include <cuda_bf16.h>
#include <cuda_fp16.h>
#include <cstdint>
#include <math.h>

#define BATCH 8
#define LSEQ  2048
#define DDIM  512

// ---------------------------------------------------------------------------
// Device-global scratch (module-load allocation; no runtime allocs).
// ---------------------------------------------------------------------------
static __device__ float g_P[(size_t)BATCH * LSEQ * LSEQ];                           // 128 MiB logits
static __device__ __align__(128) __nv_bfloat16 g_qh[(size_t)BATCH * LSEQ * DDIM];
static __device__ __align__(128) __nv_bfloat16 g_ql[(size_t)BATCH * LSEQ * DDIM];
static __device__ __align__(128) __nv_bfloat16 g_kh[(size_t)BATCH * LSEQ * DDIM];
static __device__ __align__(128) __nv_bfloat16 g_kl[(size_t)BATCH * LSEQ * DDIM];
static __device__ __align__(128) __half g_vtf[(size_t)BATCH * DDIM * LSEQ];         // v^T fp16 [b][d][j]
static __device__ __align__(128) __half g_af[(size_t)BATCH * LSEQ * LSEQ];          // attn fp16

// ---------------------------------------------------------------------------
// PTX helpers (sm_80+ only; base sm_103 target has no tcgen05)
// ---------------------------------------------------------------------------
__device__ __forceinline__ uint32_t smem_u32(const void* p) {
    uint32_t a;
    asm("{ .reg .u64 t; cvta.to.shared.u64 t, %1; cvt.u32.u64 %0, t; }" : "=r"(a) : "l"(p));
    return a;
}
__device__ __forceinline__ void ldsm4(uint32_t* r, uint32_t addr) {
    asm volatile("ldmatrix.sync.aligned.m8n8.x4.shared.b16 {%0,%1,%2,%3}, [%4];"
                 : "=r"(r[0]), "=r"(r[1]), "=r"(r[2]), "=r"(r[3]) : "r"(addr));
}
#define MMA_BF16(d, a, b0, b1)                                                     \
    asm volatile("mma.sync.aligned.m16n8k16.row.col.f32.bf16.bf16.f32 "            \
                 "{%0,%1,%2,%3},{%4,%5,%6,%7},{%8,%9},{%0,%1,%2,%3};"              \
                 : "+f"((d)[0]), "+f"((d)[1]), "+f"((d)[2]), "+f"((d)[3])          \
                 : "r"((a)[0]), "r"((a)[1]), "r"((a)[2]), "r"((a)[3]),             \
                   "r"(b0), "r"(b1))
#define MMA_F16(d, a, b0, b1)                                                      \
    asm volatile("mma.sync.aligned.m16n8k16.row.col.f32.f16.f16.f32 "              \
                 "{%0,%1,%2,%3},{%4,%5,%6,%7},{%8,%9},{%0,%1,%2,%3};"              \
                 : "+f"((d)[0]), "+f"((d)[1]), "+f"((d)[2]), "+f"((d)[3])          \
                 : "r"((a)[0]), "r"((a)[1]), "r"((a)[2]), "r"((a)[3]),             \
                   "r"(b0), "r"(b1))
#define CP_ASYNC16(dst, src) \
    asm volatile("cp.async.cg.shared.global [%0], [%1], 16;" :: "r"(dst), "l"(src))
#define CP_COMMIT()  asm volatile("cp.async.commit_group;" ::: "memory")
#define CP_WAITN(n)  asm volatile("cp.async.wait_group %0;" :: "n"(n) : "memory")

__device__ __forceinline__ void split2(float v, __nv_bfloat16& h, __nv_bfloat16& l) {
    h = __float2bfloat16(v);
    l = __float2bfloat16(v - __bfloat162float(h));
}

// Swizzle for 64-byte rows (4 x 16B segs): seg ^= (row>>1)&3
__device__ __forceinline__ uint32_t swz64(int row, int seg) {
    return (uint32_t)(row * 64 + ((seg ^ ((row >> 1) & 3)) << 4));
}
// Swizzle for 128-byte rows (8 x 16B segs): seg ^= row&7
__device__ __forceinline__ uint32_t swz128(int row, int seg) {
    return (uint32_t)(row * 128 + ((seg ^ (row & 7)) << 4));
}

// ---------------------------------------------------------------------------
// Kernel 1: split projections. q,k -> bf16 hi/lo [b][i][d]; v -> fp16 single,
// transposed [b][d][j] via smem tile transpose. Block = 64(j) x 64(d).
// ---------------------------------------------------------------------------
__global__ __launch_bounds__(256) void split_kernel(const float* __restrict__ x,
                                                    const float* __restrict__ qw,
                                                    const float* __restrict__ kw,
                                                    const float* __restrict__ vw)
{
    __shared__ __half vf_s[64][66];

    const int b  = blockIdx.z;
    const int j0 = blockIdx.x * 64;
    const int d0 = blockIdx.y * 64;
    const int t  = threadIdx.x;

    union U4 { __nv_bfloat16 h[4]; uint2 u; };

#pragma unroll
    for (int it = 0; it < 4; ++it) {
        const int id = t + it * 256;
        const int r  = id >> 4;
        const int c  = (id & 15) * 4;
        const size_t gx = ((size_t)b * LSEQ + j0 + r) * DDIM + d0 + c;
        const size_t gw = (size_t)(j0 + r) * DDIM + d0 + c;
        const float4 xv = *(const float4*)(x  + gx);
        const float4 q4 = *(const float4*)(qw + gw);
        const float4 k4 = *(const float4*)(kw + gw);
        const float4 v4 = *(const float4*)(vw + gw);

        U4 qh, ql, kh, kl;
        split2(xv.x * q4.x, qh.h[0], ql.h[0]); split2(xv.y * q4.y, qh.h[1], ql.h[1]);
        split2(xv.z * q4.z, qh.h[2], ql.h[2]); split2(xv.w * q4.w, qh.h[3], ql.h[3]);
        split2(xv.x * k4.x, kh.h[0], kl.h[0]); split2(xv.y * k4.y, kh.h[1], kl.h[1]);
        split2(xv.z * k4.z, kh.h[2], kl.h[2]); split2(xv.w * k4.w, kh.h[3], kl.h[3]);
        *(uint2*)(g_qh + gx) = qh.u;  *(uint2*)(g_ql + gx) = ql.u;
        *(uint2*)(g_kh + gx) = kh.u;  *(uint2*)(g_kl + gx) = kl.u;

        vf_s[r][c + 0] = __float2half(xv.x * v4.x);
        vf_s[r][c + 1] = __float2half(xv.y * v4.y);
        vf_s[r][c + 2] = __float2half(xv.z * v4.z);
        vf_s[r][c + 3] = __float2half(xv.w * v4.w);
    }
    __syncthreads();

#pragma unroll
    for (int it = 0; it < 16; ++it) {
        const int id = t + it * 256;
        const int dr = id >> 6;
        const int jc = id & 63;
        const size_t go = ((size_t)b * DDIM + d0 + dr) * LSEQ + j0 + jc;
        g_vtf[go] = vf_s[jc][dr];
    }
}

// ---------------------------------------------------------------------------
// Kernel 2: QK 3-product bf16 HMMA GEMM. P = scale * (Qh+Ql)(Kh+Kl)^T (lo*lo
// dropped). Tile 128x128, K-chunk 32, 3-stage cp.async, one barrier per chunk.
// ---------------------------------------------------------------------------
__global__ __launch_bounds__(256, 2) void qk_kernel(float* __restrict__ dummy)
{
    extern __shared__ __align__(128) char dsm[];

    constexpr int K       = DDIM;
    constexpr int NC      = K / 32;        // 16
    constexpr int TILE_B  = 128 * 64;      // 8 KB
    constexpr int STAGE_B = 4 * TILE_B;    // 32 KB
    const float scale = 0.3535533905932738f;

    const int b  = blockIdx.z;
    const int n0 = blockIdx.x * 128;
    const int m0 = blockIdx.y * 128;
    const int t    = threadIdx.x;
    const int lane = t & 31;
    const int wid  = t >> 5;
    const int wm   = wid & 1;
    const int wn   = wid >> 1;

    const __nv_bfloat16* pAh = g_qh + ((size_t)b * LSEQ + m0) * K;
    const __nv_bfloat16* pAl = g_ql + ((size_t)b * LSEQ + m0) * K;
    const __nv_bfloat16* pBh = g_kh + ((size_t)b * LSEQ + n0) * K;
    const __nv_bfloat16* pBl = g_kl + ((size_t)b * LSEQ + n0) * K;
    float* Cb = g_P + ((size_t)b * LSEQ + m0) * LSEQ + n0;

    const uint32_t sb = smem_u32(dsm);

    auto prefetch = [&](int c, int s) {
        const int k0 = c * 32;
        const uint32_t st = sb + s * STAGE_B;
        const __nv_bfloat16* gs[4] = { pAh + k0, pAl + k0, pBh + k0, pBl + k0 };
#pragma unroll
        for (int tt = 0; tt < 4; ++tt) {
            const uint32_t tb = st + tt * TILE_B;
#pragma unroll
            for (int i = 0; i < 2; ++i) {
                const int li  = t + i * 256;
                const int row = li >> 2;
                const int seg = li & 3;
                CP_ASYNC16(tb + swz64(row, seg), gs[tt] + (size_t)row * K + seg * 8);
            }
        }
        CP_COMMIT();
    };

    float acc[4][4][4];
#pragma unroll
    for (int mf = 0; mf < 4; ++mf)
#pragma unroll
        for (int nf = 0; nf < 4; ++nf)
#pragma unroll
            for (int i = 0; i < 4; ++i) acc[mf][nf][i] = 0.0f;

    const int lr   = lane & 15;
    const int lseg = lane >> 4;

    prefetch(0, 0);
    prefetch(1, 1);

    int s = 0;
    for (int c = 0; c < NC; ++c) {
        if (c + 1 < NC) { CP_WAITN(1); } else { CP_WAITN(0); }
        __syncthreads();

        const uint32_t st  = sb + s * STAGE_B;
        const uint32_t sAh = st;
        const uint32_t sAl = st + TILE_B;
        const uint32_t sBh = st + 2 * TILE_B;
        const uint32_t sBl = st + 3 * TILE_B;

#pragma unroll
        for (int ks = 0; ks < 2; ++ks) {
            const int segk = ks * 2 + lseg;
            uint32_t ah[4][4], al[4][4], bh[2][4], bl[2][4];
#pragma unroll
            for (int mf = 0; mf < 4; ++mf) {
                const uint32_t off = swz64(wm * 64 + mf * 16 + lr, segk);
                ldsm4(ah[mf], sAh + off);
                ldsm4(al[mf], sAl + off);
            }
#pragma unroll
            for (int p = 0; p < 2; ++p) {
                const uint32_t off = swz64(wn * 32 + p * 16 + lr, segk);
                ldsm4(bh[p], sBh + off);
                ldsm4(bl[p], sBl + off);
            }
#pragma unroll
            for (int mf = 0; mf < 4; ++mf)
#pragma unroll
                for (int nf = 0; nf < 4; ++nf) {
                    const int p = nf >> 1, s2 = nf & 1;
                    MMA_BF16(acc[mf][nf], ah[mf], bh[p][s2], bh[p][s2 + 2]);
                }
#pragma unroll
            for (int mf = 0; mf < 4; ++mf)
#pragma unroll
                for (int nf = 0; nf < 4; ++nf) {
                    const int p = nf >> 1, s2 = nf & 1;
                    MMA_BF16(acc[mf][nf], al[mf], bh[p][s2], bh[p][s2 + 2]);
                }
#pragma unroll
            for (int mf = 0; mf < 4; ++mf)
#pragma unroll
                for (int nf = 0; nf < 4; ++nf) {
                    const int p = nf >> 1, s2 = nf & 1;
                    MMA_BF16(acc[mf][nf], ah[mf], bl[p][s2], bl[p][s2 + 2]);
                }
        }

        if (c + 2 < NC) {
            int s2 = s + 2; if (s2 >= 3) s2 -= 3;
            prefetch(c + 2, s2);
        }
        if (++s == 3) s = 0;
    }

#pragma unroll
    for (int mf = 0; mf < 4; ++mf) {
#pragma unroll
        for (int nf = 0; nf < 4; ++nf) {
            const int r0 = wm * 64 + mf * 16 + (lane >> 2);
            const int cc = wn * 32 + nf * 8 + (lane & 3) * 2;
            float2 v0, v1;
            v0.x = acc[mf][nf][0] * scale; v0.y = acc[mf][nf][1] * scale;
            v1.x = acc[mf][nf][2] * scale; v1.y = acc[mf][nf][3] * scale;
            *(float2*)&Cb[(size_t)r0 * LSEQ + cc]       = v0;
            *(float2*)&Cb[(size_t)(r0 + 8) * LSEQ + cc] = v1;
        }
    }
}

// ---------------------------------------------------------------------------
// Kernel 3: row softmax over g_P -> fp16 attention g_af.
// ---------------------------------------------------------------------------
__global__ __launch_bounds__(256) void softmax_kernel()
{
    const size_t row = blockIdx.x;
    const float* p = g_P + row * LSEQ;
    const int t = threadIdx.x;

    __shared__ float red[256];

    float v[8];
    float mx = -1e30f;
#pragma unroll
    for (int i = 0; i < 8; ++i) {
        v[i] = p[t + i * 256];
        mx = fmaxf(mx, v[i]);
    }
    red[t] = mx;
    __syncthreads();
    for (int s = 128; s > 0; s >>= 1) {
        if (t < s) red[t] = fmaxf(red[t], red[t + s]);
        __syncthreads();
    }
    const float m = red[0];
    __syncthreads();

    float sum = 0.0f;
#pragma unroll
    for (int i = 0; i < 8; ++i) {
        v[i] = __expf(v[i] - m);
        sum += v[i];
    }
    red[t] = sum;
    __syncthreads();
    for (int s = 128; s > 0; s >>= 1) {
        if (t < s) red[t] += red[t + s];
        __syncthreads();
    }
    const float inv = 1.0f / red[0];
#pragma unroll
    for (int i = 0; i < 8; ++i)
        g_af[row * LSEQ + t + i * 256] = __float2half(v[i] * inv);
}

// ---------------------------------------------------------------------------
// Kernel 4: AV single-product fp16 HMMA GEMM. out = A @ V.
// Tile 128x128, K-chunk 64 (128-byte rows, SW128), 3-stage cp.async,
// one barrier per chunk. A = fp16 attention, B = fp16 v^T.
// ---------------------------------------------------------------------------
__global__ __launch_bounds__(256, 2) void av_kernel(float* __restrict__ Cout)
{
    extern __shared__ __align__(128) char dsm[];

    constexpr int K       = LSEQ;          // reduction over j
    constexpr int NC      = K / 64;        // 32
    constexpr int TILE_B  = 128 * 128;     // 16 KB
    constexpr int STAGE_B = 2 * TILE_B;    // 32 KB

    const int b  = blockIdx.z;
    const int n0 = blockIdx.x * 128;       // output feature cols (D)
    const int m0 = blockIdx.y * 128;       // query rows
    const int t    = threadIdx.x;
    const int lane = t & 31;
    const int wid  = t >> 5;
    const int wm   = wid & 1;
    const int wn   = wid >> 1;

    const __half* pA = g_af  + ((size_t)b * LSEQ + m0) * LSEQ;   // row stride LSEQ
    const __half* pB = g_vtf + ((size_t)b * DDIM + n0) * LSEQ;   // row stride LSEQ
    float* Cb = Cout + ((size_t)b * LSEQ + m0) * DDIM + n0;

    const uint32_t sb = smem_u32(dsm);

    auto prefetch = [&](int c, int s) {
        const int k0 = c * 64;
        const uint32_t st = sb + s * STAGE_B;
        const __half* gs[2] = { pA + k0, pB + k0 };
#pragma unroll
        for (int tt = 0; tt < 2; ++tt) {
            const uint32_t tb = st + tt * TILE_B;
#pragma unroll
            for (int i = 0; i < 4; ++i) {
                const int li  = t + i * 256;     // 0..1023
                const int row = li >> 3;
                const int seg = li & 7;
                CP_ASYNC16(tb + swz128(row, seg), gs[tt] + (size_t)row * LSEQ + seg * 8);
            }
        }
        CP_COMMIT();
    };

    float acc[4][4][4];
#pragma unroll
    for (int mf = 0; mf < 4; ++mf)
#pragma unroll
        for (int nf = 0; nf < 4; ++nf)
#pragma unroll
            for (int i = 0; i < 4; ++i) acc[mf][nf][i] = 0.0f;

    const int lr   = lane & 15;
    const int lseg = lane >> 4;

    prefetch(0, 0);
    prefetch(1, 1);

    int s = 0;
    for (int c = 0; c < NC; ++c) {
        if (c + 1 < NC) { CP_WAITN(1); } else { CP_WAITN(0); }
        __syncthreads();

        const uint32_t sA = sb + s * STAGE_B;
        const uint32_t sB = sA + TILE_B;

#pragma unroll
        for (int ks = 0; ks < 4; ++ks) {
            const int segk = ks * 2 + lseg;
            uint32_t a[4][4], bb[2][4];
#pragma unroll
            for (int mf = 0; mf < 4; ++mf)
                ldsm4(a[mf], sA + swz128(wm * 64 + mf * 16 + lr, segk));
#pragma unroll
            for (int p = 0; p < 2; ++p)
                ldsm4(bb[p], sB + swz128(wn * 32 + p * 16 + lr, segk));
#pragma unroll
            for (int mf = 0; mf < 4; ++mf)
#pragma unroll
                for (int nf = 0; nf < 4; ++nf) {
                    const int p = nf >> 1, s2 = nf & 1;
                    MMA_F16(acc[mf][nf], a[mf], bb[p][s2], bb[p][s2 + 2]);
                }
        }

        if (c + 2 < NC) {
            int s2 = s + 2; if (s2 >= 3) s2 -= 3;
            prefetch(c + 2, s2);
        }
        if (++s == 3) s = 0;
    }

#pragma unroll
    for (int mf = 0; mf < 4; ++mf) {
#pragma unroll
        for (int nf = 0; nf < 4; ++nf) {
            const int r0 = wm * 64 + mf * 16 + (lane >> 2);
            const int cc = wn * 32 + nf * 8 + (lane & 3) * 2;
            float2 v0, v1;
            v0.x = acc[mf][nf][0]; v0.y = acc[mf][nf][1];
            v1.x = acc[mf][nf][2]; v1.y = acc[mf][nf][3];
            *(float2*)&Cb[(size_t)r0 * DDIM + cc]       = v0;
            *(float2*)&Cb[(size_t)(r0 + 8) * DDIM + cc] = v1;
        }
    }
}

// ---------------------------------------------------------------------------
extern "C" void kernel_launch(void* const* d_in, const int* in_sizes, int n_in,
                              void* d_out, int out_size)
{
    const float* x  = (const float*)d_in[0];
    const float* qw = (const float*)d_in[1];
    const float* kw = (const float*)d_in[2];
    const float* vw = (const float*)d_in[3];
    float* out = (float*)d_out;

    constexpr int SMEM = 98304;   // 3 stages x 32 KB
    cudaFuncSetAttribute(qk_kernel, cudaFuncAttributeMaxDynamicSharedMemorySize, SMEM);
    cudaFuncSetAttribute(av_kernel, cudaFuncAttributeMaxDynamicSharedMemorySize, SMEM);

    split_kernel<<<dim3(LSEQ / 64, DDIM / 64, BATCH), 256>>>(x, qw, kw, vw);

    qk_kernel<<<dim3(LSEQ / 128, LSEQ / 128, BATCH), 256, SMEM>>>(nullptr);

    softmax_kernel<<<BATCH * LSEQ, 256>>>();

    av_kernel<<<dim3(DDIM / 128, LSEQ / 128, BATCH), 256, SMEM>>>(out);
}